// round 7
// baseline (speedup 1.0000x reference)
#include <cuda_runtime.h>

#define NTAGS 64
#define SOS_IDX 1
#define EOS_IDX 2
#define REF_TAG 3

static __device__ __forceinline__ unsigned long long pk2(float x, float y) {
    unsigned long long r;
    asm("mov.b64 %0, {%1, %2};" : "=l"(r) : "f"(x), "f"(y));
    return r;
}
static __device__ __forceinline__ void upk2(unsigned long long a, float &x, float &y) {
    asm("mov.b64 {%0, %1}, %2;" : "=f"(x), "=f"(y) : "l"(a));
}
static __device__ __forceinline__ unsigned long long fma2(unsigned long long a,
                                                          unsigned long long b,
                                                          unsigned long long c) {
    unsigned long long d;
    asm("fma.rn.f32x2 %0, %1, %2, %3;" : "=l"(d) : "l"(a), "l"(b), "l"(c));
    return d;
}
static __device__ __forceinline__ unsigned long long add2(unsigned long long a,
                                                          unsigned long long b) {
    unsigned long long d;
    asm("add.rn.f32x2 %0, %1, %2;" : "=l"(d) : "l"(a), "l"(b));
    return d;
}

struct Chain {
    const float* hb;
    float rawh[4];
    float ehcur;
    float myu;
    int Esum;
};

// One step of one chain. upv/unv are this chain's double-buffered U arrays.
static __device__ __forceinline__ void chain_step(
    Chain& c, const unsigned long long* E2, int i, int t, int T,
    const float* up, float* un)
{
    int tp = t + 4;
    tp = (tp < T) ? tp : (T - 1);
    float fresh = c.hb[(size_t)tp * NTAGS];
    float ehnext = __expf(c.rawh[(t + 1) & 3]);     // operand loaded at t-3
    c.rawh[t & 3] = fresh;
    const float eh = c.ehcur;
    c.ehcur = ehnext;

    const float4* pv = reinterpret_cast<const float4*>(up);
    unsigned long long acc[8];
    float4 pa[8];
    #pragma unroll
    for (int k = 0; k < 8; k++) pa[k] = pv[k];          // j = 0..31

    // exact power-of-two renormalizer (ALU-only, off the dot path)
    const unsigned int ub = __float_as_uint(up[REF_TAG]);
    int e = (int)((ub >> 23) & 0xffu) - 127;
    e = (ub == 0u) ? 0 : e;
    const float scale = __uint_as_float((unsigned)(127 - e) << 23);
    c.Esum += e;
    const float es = eh * scale;

    #pragma unroll
    for (int k = 0; k < 8; k++) {
        const int a0 = (k & 3) * 2;
        unsigned long long lo = fma2(E2[2 * k],     pk2(pa[k].x, pa[k].y),
                                     (k < 4) ? 0ull : acc[a0]);
        unsigned long long hi = fma2(E2[2 * k + 1], pk2(pa[k].z, pa[k].w),
                                     (k < 4) ? 0ull : acc[a0 + 1]);
        acc[a0] = lo; acc[a0 + 1] = hi;
    }
    #pragma unroll
    for (int k = 0; k < 8; k++) pa[k] = pv[k + 8];      // j = 32..63
    #pragma unroll
    for (int k = 0; k < 8; k++) {
        const int a0 = (k & 3) * 2;
        acc[a0]     = fma2(E2[2 * (k + 8)],     pk2(pa[k].x, pa[k].y), acc[a0]);
        acc[a0 + 1] = fma2(E2[2 * (k + 8) + 1], pk2(pa[k].z, pa[k].w), acc[a0 + 1]);
    }
    unsigned long long sA = add2(add2(add2(acc[0], acc[2]), add2(acc[4], acc[6])),
                                 add2(add2(acc[1], acc[3]), add2(acc[5], acc[7])));
    float vx, vy;
    upk2(sA, vx, vy);
    const float u = es * (vx + vy);
    un[i] = u;
    c.myu = u;
}

__global__ void __launch_bounds__(NTAGS) crf_fwd_kernel(
    const float* __restrict__ h, const float* __restrict__ mask,
    const float* __restrict__ trans, float* __restrict__ out, int T, int B)
{
    const int i = threadIdx.x;          // one thread per tag
    const int warp = i >> 5;
    const int lane = i & 31;
    const int half = gridDim.x;         // = ceil(B/2)
    const int b0 = blockIdx.x;
    const int b1 = blockIdx.x + half;
    const bool has1 = (b1 < B);

    __shared__ __align__(16) float sh_u0[2][NTAGS];
    __shared__ __align__(16) float sh_u1[2][NTAGS];
    __shared__ float sh_red[4];

    // ---- lengths (mask is a prefix of ones) ----
    float ms0 = 0.0f, ms1 = 0.0f;
    {
        const float4* m0 = reinterpret_cast<const float4*>(mask + (size_t)b0 * T);
        const float4* m1 = reinterpret_cast<const float4*>(mask + (size_t)(has1 ? b1 : b0) * T);
        const int n4 = T >> 2;
        for (int k = i; k < n4; k += NTAGS) {
            float4 v0 = m0[k]; ms0 += (v0.x + v0.y) + (v0.z + v0.w);
            float4 v1 = m1[k]; ms1 += (v1.x + v1.y) + (v1.z + v1.w);
        }
        #pragma unroll
        for (int o = 16; o > 0; o >>= 1) {
            ms0 += __shfl_xor_sync(0xffffffffu, ms0, o);
            ms1 += __shfl_xor_sync(0xffffffffu, ms1, o);
        }
        if (lane == 0) { sh_red[warp] = ms0; sh_red[2 + warp] = ms1; }
    }

    // E[i][j] = exp(trans[i][j]) packed as f32x2 (shared by both chains).
    unsigned long long E2[NTAGS / 2];
    {
        const float4* tr = reinterpret_cast<const float4*>(trans + i * NTAGS);
        #pragma unroll
        for (int k = 0; k < NTAGS / 4; k++) {
            float4 t4 = tr[k];
            E2[2 * k]     = pk2(__expf(t4.x), __expf(t4.y));
            E2[2 * k + 1] = pk2(__expf(t4.z), __expf(t4.w));
        }
    }
    const float eeos = __expf(trans[EOS_IDX * NTAGS + i]);

    __syncthreads();
    const int len0 = (int)(sh_red[0] + sh_red[1] + 0.5f);
    const int len1 = has1 ? (int)(sh_red[2] + sh_red[3] + 0.5f) : 0;
    const int lenmax = (len0 > len1) ? len0 : len1;

    Chain c0, c1;
    c0.hb = h + (size_t)b0 * T * NTAGS + i;
    c1.hb = h + (size_t)(has1 ? b1 : b0) * T * NTAGS + i;
    #pragma unroll
    for (int k = 0; k < 4; k++) {
        int tp = (k < T) ? k : (T - 1);
        c0.rawh[k] = c0.hb[(size_t)tp * NTAGS];
        c1.rawh[k] = c1.hb[(size_t)tp * NTAGS];
    }
    c0.ehcur = __expf(c0.rawh[0]);
    c1.ehcur = __expf(c1.rawh[0]);
    c0.myu = c1.myu = (i == SOS_IDX) ? 1.0f : 0.0f;
    c0.Esum = c1.Esum = 0;
    sh_u0[0][i] = c0.myu;
    sh_u1[0][i] = c1.myu;
    __syncthreads();

    #pragma unroll 2
    for (int t = 0; t < lenmax; t++) {
        if (t < len0)                                   // CTA-uniform branch
            chain_step(c0, E2, i, t, T, sh_u0[t & 1], sh_u0[(t + 1) & 1]);
        if (t < len1)                                   // CTA-uniform branch
            chain_step(c1, E2, i, t, T, sh_u1[t & 1], sh_u1[(t + 1) & 1]);
        __syncthreads();                                // one barrier, two steps
    }

    // finals: out[b] = Esum*ln2 + log(sum_i U_i * exp(trans[EOS,i]))
    float t0 = c0.myu * eeos;
    float t1 = c1.myu * eeos;
    #pragma unroll
    for (int o = 16; o > 0; o >>= 1) {
        t0 += __shfl_xor_sync(0xffffffffu, t0, o);
        t1 += __shfl_xor_sync(0xffffffffu, t1, o);
    }
    __syncthreads();
    if (lane == 0) { sh_red[warp] = t0; sh_red[2 + warp] = t1; }
    __syncthreads();
    if (i == 0) {
        out[b0] = (float)c0.Esum * 0.6931471805599453f + __logf(sh_red[0] + sh_red[1]);
        if (has1)
            out[b1] = (float)c1.Esum * 0.6931471805599453f + __logf(sh_red[2] + sh_red[3]);
    }
}

extern "C" void kernel_launch(void* const* d_in, const int* in_sizes, int n_in,
                              void* d_out, int out_size) {
    const float* h     = (const float*)d_in[0];   // [B, T, 64]
    const float* mask  = (const float*)d_in[1];   // [B, T]
    const float* trans = (const float*)d_in[2];   // [64, 64]
    float* out = (float*)d_out;                   // [B]
    const int B = out_size;
    const int T = in_sizes[1] / B;
    const int grid = (B + 1) / 2;
    crf_fwd_kernel<<<grid, NTAGS>>>(h, mask, trans, out, T, B);
}

// round 8
// speedup vs baseline: 2.2964x; 2.2964x over previous
#include <cuda_runtime.h>

#define NTAGS 64
#define SOS_IDX 1
#define EOS_IDX 2
#define REF_TAG 3

static __device__ __forceinline__ unsigned long long pk2(float x, float y) {
    unsigned long long r;
    asm("mov.b64 %0, {%1, %2};" : "=l"(r) : "f"(x), "f"(y));
    return r;
}
static __device__ __forceinline__ void upk2(unsigned long long a, float &x, float &y) {
    asm("mov.b64 {%0, %1}, %2;" : "=f"(x), "=f"(y) : "l"(a));
}
static __device__ __forceinline__ unsigned long long fma2(unsigned long long a,
                                                          unsigned long long b,
                                                          unsigned long long c) {
    unsigned long long d;
    asm("fma.rn.f32x2 %0, %1, %2, %3;" : "=l"(d) : "l"(a), "l"(b), "l"(c));
    return d;
}
static __device__ __forceinline__ unsigned long long add2(unsigned long long a,
                                                          unsigned long long b) {
    unsigned long long d;
    asm("add.rn.f32x2 %0, %1, %2;" : "=l"(d) : "l"(a), "l"(b));
    return d;
}
// named barrier: synchronize 64 threads (2 warps) on barrier id `bid`
static __device__ __forceinline__ void bar_named(int bid) {
    asm volatile("bar.sync %0, 64;" :: "r"(bid) : "memory");
}

__global__ void __launch_bounds__(128) crf_fwd_kernel(
    const float* __restrict__ h, const float* __restrict__ mask,
    const float* __restrict__ trans, float* __restrict__ out, int T, int B)
{
    const int tid = threadIdx.x;
    const int chain = tid >> 6;         // 0: warps 0-1, 1: warps 2-3
    const int i = tid & 63;             // tag index within the chain group
    const int warp = i >> 5;
    const int lane = i & 31;
    const int bid = 1 + chain;          // named barrier id for this chain

    const int b = blockIdx.x + chain * gridDim.x;
    const bool active = (b < B);
    const int bsafe = active ? b : 0;

    __shared__ __align__(16) float sh_u[2][2][NTAGS];   // [chain][buf][tag]
    __shared__ float sh_red[2][2];                      // [chain][warp]

    // ---- len = sum(mask[b,:]) (mask is a prefix of ones), per chain group ----
    const float* mb = mask + (size_t)bsafe * T;
    float msum = 0.0f;
    {
        const float4* m4 = reinterpret_cast<const float4*>(mb);
        const int n4 = T >> 2;
        for (int k = i; k < n4; k += NTAGS) {
            float4 v = m4[k];
            msum += (v.x + v.y) + (v.z + v.w);
        }
        #pragma unroll
        for (int o = 16; o > 0; o >>= 1) msum += __shfl_xor_sync(0xffffffffu, msum, o);
        if (lane == 0) sh_red[chain][warp] = msum;
    }

    // E[i][j] = exp(trans[i][j]) packed as f32x2 (constant over t).
    // exp(-10000) underflows to exactly 0 -> masked transitions vanish.
    unsigned long long E2[NTAGS / 2];
    {
        const float4* tr = reinterpret_cast<const float4*>(trans + i * NTAGS);
        #pragma unroll
        for (int k = 0; k < NTAGS / 4; k++) {
            float4 t4 = tr[k];
            E2[2 * k]     = pk2(__expf(t4.x), __expf(t4.y));
            E2[2 * k + 1] = pk2(__expf(t4.z), __expf(t4.w));
        }
    }
    const float eeos = __expf(trans[EOS_IDX * NTAGS + i]);

    const float* hb = h + (size_t)bsafe * T * NTAGS + i;

    bar_named(bid);
    const int len = active ? (int)(sh_red[chain][0] + sh_red[chain][1] + 0.5f) : 0;

    // raw prefetch buffers (depth 4)
    float rawh[4];
    #pragma unroll
    for (int k = 0; k < 4; k++) {
        int tp = (k < T) ? k : (T - 1);
        rawh[k] = hb[(size_t)tp * NTAGS];
    }

    // U(-1): 1 at SOS, 0 elsewhere.
    sh_u[chain][0][i] = (i == SOS_IDX) ? 1.0f : 0.0f;
    float myu = (i == SOS_IDX) ? 1.0f : 0.0f;
    int Esum = 0;
    float ehcur = __expf(rawh[0]);      // exp computed one full step ahead
    bar_named(bid);

    #pragma unroll 4
    for (int t = 0; t < len; t++) {
        // prefetch h for t+4 (clamped, always in-bounds) and exp for t+1
        int tp = t + 4;
        tp = (tp < T) ? tp : (T - 1);
        float fresh = hb[(size_t)tp * NTAGS];
        float ehnext = __expf(rawh[(t + 1) & 3]);   // operand loaded at t-3
        rawh[t & 3] = fresh;
        const float eh = ehcur;
        ehcur = ehnext;

        const float* up = sh_u[chain][t & 1];
        float* un = sh_u[chain][(t + 1) & 1];
        const float4* pv = reinterpret_cast<const float4*>(up);

        // w_i = dot(E_row_i, U_prev): two front-batched groups of 8 LDS.128,
        // 32 packed f32x2 FMAs into 8 independent accumulators.
        unsigned long long acc[8];
        float4 pa[8];
        #pragma unroll
        for (int k = 0; k < 8; k++) pa[k] = pv[k];          // j = 0..31

        // exact power-of-two renormalizer (ALU-only, off the dot path)
        const unsigned int ub = __float_as_uint(up[REF_TAG]);
        int e = (int)((ub >> 23) & 0xffu) - 127;
        e = (ub == 0u) ? 0 : e;             // t==0: uref is exactly 0
        const float scale = __uint_as_float((unsigned)(127 - e) << 23);
        Esum += e;
        const float es = eh * scale;

        #pragma unroll
        for (int k = 0; k < 8; k++) {
            const int a0 = (k & 3) * 2;
            unsigned long long lo = fma2(E2[2 * k],     pk2(pa[k].x, pa[k].y),
                                         (k < 4) ? 0ull : acc[a0]);
            unsigned long long hi = fma2(E2[2 * k + 1], pk2(pa[k].z, pa[k].w),
                                         (k < 4) ? 0ull : acc[a0 + 1]);
            acc[a0] = lo; acc[a0 + 1] = hi;
        }
        #pragma unroll
        for (int k = 0; k < 8; k++) pa[k] = pv[k + 8];      // j = 32..63
        #pragma unroll
        for (int k = 0; k < 8; k++) {
            const int a0 = (k & 3) * 2;
            acc[a0]     = fma2(E2[2 * (k + 8)],     pk2(pa[k].x, pa[k].y), acc[a0]);
            acc[a0 + 1] = fma2(E2[2 * (k + 8) + 1], pk2(pa[k].z, pa[k].w), acc[a0 + 1]);
        }
        unsigned long long sA = add2(add2(add2(acc[0], acc[2]), add2(acc[4], acc[6])),
                                     add2(add2(acc[1], acc[3]), add2(acc[5], acc[7])));
        float vx, vy;
        upk2(sA, vx, vy);
        const float w = vx + vy;

        const float u = es * w;             // U_i(t)
        un[i] = u;
        myu = u;
        bar_named(bid);                     // 2-warp named barrier per step
    }

    // out[b] = Esum*ln2 + log( sum_i U_i * exp(trans[EOS,i]) )
    float term = myu * eeos;
    #pragma unroll
    for (int o = 16; o > 0; o >>= 1) term += __shfl_xor_sync(0xffffffffu, term, o);
    bar_named(bid);                         // sh_red reuse safety
    if (lane == 0) sh_red[chain][warp] = term;
    bar_named(bid);
    if (i == 0 && active) {
        out[b] = (float)Esum * 0.6931471805599453f +
                 __logf(sh_red[chain][0] + sh_red[chain][1]);
    }
}

extern "C" void kernel_launch(void* const* d_in, const int* in_sizes, int n_in,
                              void* d_out, int out_size) {
    const float* h     = (const float*)d_in[0];   // [B, T, 64]
    const float* mask  = (const float*)d_in[1];   // [B, T]
    const float* trans = (const float*)d_in[2];   // [64, 64]
    float* out = (float*)d_out;                   // [B]
    const int B = out_size;
    const int T = in_sizes[1] / B;
    const int grid = (B + 1) / 2;
    crf_fwd_kernel<<<grid, 128>>>(h, mask, trans, out, T, B);
}